// round 7
// baseline (speedup 1.0000x reference)
#include <cuda_runtime.h>
#include <cuda_bf16.h>
#include <cstdint>

#define TSTEPS 500
#define BATCH  64
#define INDIM  440
#define INPAD  448
#define HID    1024
#define OUTDIM 1944
#define ROWS   (TSTEPS * BATCH)   // 32000

// ---------------------------------------------------------------------------
// Scratch (static device globals; no runtime allocation allowed)
// ---------------------------------------------------------------------------
__device__ __align__(16) int8_t g_act[(size_t)ROWS * HID];   // activations (int8 spikes 0..7)
__device__ __align__(16) float  g_ws [(size_t)ROWS * HID];   // pre-scan dense outputs
__device__ __align__(16) int8_t g_W0q1[HID * INPAD];
__device__ __align__(16) int8_t g_W0q2[HID * INPAD];
__device__ __align__(16) int8_t g_Wsq1[3 * HID * HID];
__device__ __align__(16) int8_t g_Wsq2[3 * HID * HID];
__device__ __align__(16) int8_t g_Wfq1[OUTDIM * HID];
__device__ __align__(16) int8_t g_Wfq2[OUTDIM * HID];
__device__ float g_s1[6144];    // W0 @0, Ws @1024(+1024/layer), Wf @4096
__device__ float g_s2[6144];

// ---------------------------------------------------------------------------
// Per-row int8 dual quantization:
//   s1 = amax/127;  q1 = rint(w/s1);  res = w - s1*q1
//   s2 = rmax/127;  q2 = rint(res/s2)   (=> |w - s1q1 - s2q2| <= s2/2)
// One block (256 threads) per output row. K padded with zeros to colsPad.
// ---------------------------------------------------------------------------
__global__ void __launch_bounds__(256)
quantize_rows(const float* __restrict__ W, int8_t* __restrict__ q1,
              int8_t* __restrict__ q2, float* __restrict__ s1,
              float* __restrict__ s2, int cols, int colsPad) {
    const int r = blockIdx.x, tid = threadIdx.x;
    const float* w = W + (size_t)r * cols;
    __shared__ float sred[8];
    __shared__ float sA1, sA2;

    float v[4];
    float amax = 0.0f;
#pragma unroll
    for (int j = 0; j < 4; j++) {
        int i = tid + j * 256;
        float x = (i < cols) ? w[i] : 0.0f;
        v[j] = x;
        amax = fmaxf(amax, fabsf(x));
    }
#pragma unroll
    for (int o = 16; o; o >>= 1) amax = fmaxf(amax, __shfl_xor_sync(~0u, amax, o));
    if ((tid & 31) == 0) sred[tid >> 5] = amax;
    __syncthreads();
    if (tid < 32) {
        float a = (tid < 8) ? sred[tid] : 0.0f;
#pragma unroll
        for (int o = 4; o; o >>= 1) a = fmaxf(a, __shfl_xor_sync(~0u, a, o));
        if (tid == 0) sA1 = a;
    }
    __syncthreads();
    const float A1 = sA1;
    const float S1 = (A1 > 0.0f) ? A1 * (1.0f / 127.0f) : 1.0f;
    const float i1 = 1.0f / S1;

    float qv1[4], res[4];
    float rmax = 0.0f;
#pragma unroll
    for (int j = 0; j < 4; j++) {
        float q = rintf(v[j] * i1);
        qv1[j] = q;
        res[j] = v[j] - S1 * q;
        rmax = fmaxf(rmax, fabsf(res[j]));
    }
#pragma unroll
    for (int o = 16; o; o >>= 1) rmax = fmaxf(rmax, __shfl_xor_sync(~0u, rmax, o));
    __syncthreads();
    if ((tid & 31) == 0) sred[tid >> 5] = rmax;
    __syncthreads();
    if (tid < 32) {
        float a = (tid < 8) ? sred[tid] : 0.0f;
#pragma unroll
        for (int o = 4; o; o >>= 1) a = fmaxf(a, __shfl_xor_sync(~0u, a, o));
        if (tid == 0) sA2 = a;
    }
    __syncthreads();
    const float A2 = sA2;
    const float S2 = (A2 > 0.0f) ? A2 * (1.0f / 127.0f) : 1.0f;
    const float i2 = 1.0f / S2;

#pragma unroll
    for (int j = 0; j < 4; j++) {
        int i = tid + j * 256;
        if (i < colsPad) {
            q1[(size_t)r * colsPad + i] = (int8_t)qv1[j];
            q2[(size_t)r * colsPad + i] = (int8_t)rintf(res[j] * i2);
        }
    }
    if (tid == 0) { s1[r] = S1; s2[r] = S2; }
}

// ---------------------------------------------------------------------------
// Input FSQ scan: vmem += x; q = clip(rint(vmem),0,7); out=q; vmem -= q
// One thread per (b, i) channel, sequential over T (8-deep load batching).
// ---------------------------------------------------------------------------
__global__ void __launch_bounds__(128)
input_scan_kernel(const float* __restrict__ xs, int8_t* __restrict__ act) {
    int tid = blockIdx.x * blockDim.x + threadIdx.x;
    if (tid >= BATCH * INPAD) return;
    int b = tid / INPAD, i = tid % INPAD;
    int8_t* op = act + (size_t)b * INPAD + i;
    const int strideO = BATCH * INPAD;
    if (i >= INDIM) {
        for (int t = 0; t < TSTEPS; t++) op[t * strideO] = 0;
        return;
    }
    const float* xp = xs + (size_t)b * INDIM + i;
    const int strideX = BATCH * INDIM;
    float vmem = 0.0f;
#define ISTEP(X, TT) { vmem = __fadd_rn(vmem, (X)); \
        float q = fminf(7.0f, fmaxf(0.0f, rintf(vmem))); \
        op[(TT) * strideO] = (int8_t)q; \
        vmem = __fsub_rn(vmem, q); }
    int t = 0;
    for (; t + 8 <= TSTEPS; t += 8) {
        float x[8];
#pragma unroll
        for (int j = 0; j < 8; j++) x[j] = xp[(t + j) * strideX];
#pragma unroll
        for (int j = 0; j < 8; j++) ISTEP(x[j], t + j)
    }
    for (; t < TSTEPS; t++) { float x = xp[t * strideX]; ISTEP(x, t) }
#undef ISTEP
}

// ---------------------------------------------------------------------------
// LIF scan: syn = w + tau*syn; vmem += syn; q = clip(rint(vmem),0,7); vmem -= q
// One thread per (b, h) channel.
// ---------------------------------------------------------------------------
__global__ void __launch_bounds__(128)
lif_scan_kernel(const float* __restrict__ ws, const float* __restrict__ taus,
                int8_t* __restrict__ act) {
    int tid = blockIdx.x * blockDim.x + threadIdx.x;
    if (tid >= BATCH * HID) return;
    int b = tid / HID, h = tid % HID;
    float tau = taus[h];
    const float* wp = ws + (size_t)b * HID + h;
    int8_t* op = act + (size_t)b * HID + h;
    const int stride = BATCH * HID;
    float syn = 0.0f, vmem = 0.0f;
#define LSTEP(W, TT) { syn = __fadd_rn((W), __fmul_rn(tau, syn)); \
        vmem = __fadd_rn(vmem, syn); \
        float q = fminf(7.0f, fmaxf(0.0f, rintf(vmem))); \
        op[(TT) * stride] = (int8_t)q; \
        vmem = __fsub_rn(vmem, q); }
    int t = 0;
    for (; t + 8 <= TSTEPS; t += 8) {
        float w[8];
#pragma unroll
        for (int j = 0; j < 8; j++) w[j] = wp[(t + j) * stride];
#pragma unroll
        for (int j = 0; j < 8; j++) LSTEP(w[j], t + j)
    }
    for (; t < TSTEPS; t++) { float w = wp[t * stride]; LSTEP(w, t) }
#undef LSTEP
}

// ---------------------------------------------------------------------------
// GEMM: C[M,N] = A[M,K](s8) * (s1*Q1 + s2*Q2)[N,K]^T, fused BN epilogue.
// mma.sync m16n8k32 s8, 128x128x64 CTA tile, 3-stage cp.async pipeline.
// ---------------------------------------------------------------------------
#define BM 128
#define BN 128
#define BK 64                               // int8 elements (= bytes) per k-tile
#define GSTAGES 3
#define LDSB 80                             // bytes per smem row (64 + 16 pad)
#define STAGE_ONE_BYTES (128 * LDSB)        // 10240 per matrix
#define STAGE_BYTES (3 * STAGE_ONE_BYTES)   // A | B1 | B2
#define GEMM_SMEM (GSTAGES * STAGE_BYTES)   // 92160

__device__ __forceinline__ void cp_async16(uint32_t dst, const void* src, bool pred) {
    int bytes = pred ? 16 : 0;
    asm volatile("cp.async.cg.shared.global [%0], [%1], 16, %2;\n"
                 :: "r"(dst), "l"(src), "r"(bytes));
}
__device__ __forceinline__ void ldm4(uint32_t* r, uint32_t addr) {
    asm volatile("ldmatrix.sync.aligned.m8n8.x4.shared.b16 {%0,%1,%2,%3}, [%4];\n"
                 : "=r"(r[0]), "=r"(r[1]), "=r"(r[2]), "=r"(r[3]) : "r"(addr));
}
__device__ __forceinline__ void mma_s8(int* c, const uint32_t* a, uint32_t b0, uint32_t b1) {
    asm volatile("mma.sync.aligned.m16n8k32.row.col.s32.s8.s8.s32 "
                 "{%0,%1,%2,%3}, {%4,%5,%6,%7}, {%8,%9}, {%0,%1,%2,%3};\n"
                 : "+r"(c[0]), "+r"(c[1]), "+r"(c[2]), "+r"(c[3])
                 : "r"(a[0]), "r"(a[1]), "r"(a[2]), "r"(a[3]), "r"(b0), "r"(b1));
}

__global__ void __launch_bounds__(256, 1)
gemm_bn_s8(const int8_t* __restrict__ A,
           const int8_t* __restrict__ B1,
           const int8_t* __restrict__ B2,
           float* __restrict__ C,
           int N, int K,
           const float* __restrict__ s1, const float* __restrict__ s2,
           const float* __restrict__ gamma, const float* __restrict__ beta) {
    extern __shared__ __align__(16) int8_t smem_buf[];
    const int tid = threadIdx.x;
    const int lane = tid & 31, warp = tid >> 5;
    const int wm = warp >> 1;      // 0..3 -> 32 rows of M each
    const int wn = warp & 1;       // 0..1 -> 64 cols of N each
    const int m0 = blockIdx.x * BM;
    const int n0 = blockIdx.y * BN;
    const int KT = K / BK;
    const uint32_t sbase = (uint32_t)__cvta_generic_to_shared(smem_buf);

    // ldmatrix per-lane tile addressing (matrix idx = lane>>3)
    const int mat  = lane >> 3;
    const int roff = ((mat & 1) << 3) | (lane & 7);   // +0/+8 row within 16-row group
    const int koff = (mat >> 1) << 4;                 // +0/+16 byte column

    int accH[2][8][4] = {};
    int accL[2][8][4] = {};

    auto issue_stage = [&](int kt, int s) {
        if (kt < KT) {
            const int kk = kt * BK;
            const uint32_t sA  = sbase + s * STAGE_BYTES;
            const uint32_t sB1 = sA + STAGE_ONE_BYTES;
            const uint32_t sB2 = sB1 + STAGE_ONE_BYTES;
#pragma unroll
            for (int i = 0; i < 2; i++) {
                int c = tid + i * 256;
                int r = c >> 2, col = c & 3;
                cp_async16(sA + (uint32_t)(r * LDSB + col * 16),
                           A + (size_t)(m0 + r) * K + kk + col * 16, true);
            }
#pragma unroll
            for (int i = 0; i < 2; i++) {
                int c = tid + i * 256;
                int r = c >> 2, col = c & 3;
                bool pred = (n0 + r) < N;
                int rr = pred ? (n0 + r) : 0;
                cp_async16(sB1 + (uint32_t)(r * LDSB + col * 16),
                           B1 + (size_t)rr * K + kk + col * 16, pred);
                cp_async16(sB2 + (uint32_t)(r * LDSB + col * 16),
                           B2 + (size_t)rr * K + kk + col * 16, pred);
            }
        }
        asm volatile("cp.async.commit_group;\n" ::);
    };

    auto compute_stage = [&](int s) {
        const uint32_t aB  = sbase + s * STAGE_BYTES;
        const uint32_t b1B = aB + STAGE_ONE_BYTES;
        const uint32_t b2B = b1B + STAGE_ONE_BYTES;
#pragma unroll
        for (int k32 = 0; k32 < 2; k32++) {
            uint32_t afr[2][4];
#pragma unroll
            for (int mi = 0; mi < 2; mi++)
                ldm4(afr[mi], aB + (uint32_t)((wm * 32 + mi * 16 + roff) * LDSB + k32 * 32 + koff));
#pragma unroll
            for (int nj = 0; nj < 4; nj++) {
                uint32_t boff = (uint32_t)((wn * 64 + nj * 16 + roff) * LDSB + k32 * 32 + koff);
                uint32_t bfr[4], lfr[4];
                ldm4(bfr, b1B + boff);
                ldm4(lfr, b2B + boff);
                mma_s8(accH[0][2 * nj + 0], afr[0], bfr[0], bfr[2]);
                mma_s8(accH[1][2 * nj + 0], afr[1], bfr[0], bfr[2]);
                mma_s8(accH[0][2 * nj + 1], afr[0], bfr[1], bfr[3]);
                mma_s8(accH[1][2 * nj + 1], afr[1], bfr[1], bfr[3]);
                mma_s8(accL[0][2 * nj + 0], afr[0], lfr[0], lfr[2]);
                mma_s8(accL[1][2 * nj + 0], afr[1], lfr[0], lfr[2]);
                mma_s8(accL[0][2 * nj + 1], afr[0], lfr[1], lfr[3]);
                mma_s8(accL[1][2 * nj + 1], afr[1], lfr[1], lfr[3]);
            }
        }
    };

#pragma unroll
    for (int s = 0; s < GSTAGES - 1; s++) issue_stage(s, s);

    for (int kt = 0; kt < KT; kt++) {
        asm volatile("cp.async.wait_group 1;\n" ::);
        __syncthreads();
        compute_stage(kt % GSTAGES);
        issue_stage(kt + GSTAGES - 1, (kt + GSTAGES - 1) % GSTAGES);
    }
    asm volatile("cp.async.wait_group 0;\n" ::);

    // Epilogue: out = (acc1*s1[n] + acc2*s2[n]) * gamma[n]*inv + beta[n]
    const float inv = rsqrtf(1.0f + 1e-5f);
    const int qr = lane >> 2;
    const int qc = (lane & 3) << 1;
#pragma unroll
    for (int ni = 0; ni < 8; ni++) {
        int n = n0 + wn * 64 + ni * 8 + qc;
        if (n >= N) continue;
        float g0  = gamma[n] * inv;
        float e10 = s1[n] * g0, e20 = s2[n] * g0, b0v = beta[n];
        bool has2 = (n + 1 < N);
        float e11 = 0.0f, e21 = 0.0f, b1v = 0.0f;
        if (has2) {
            float g1 = gamma[n + 1] * inv;
            e11 = s1[n + 1] * g1; e21 = s2[n + 1] * g1; b1v = beta[n + 1];
        }
#pragma unroll
        for (int mi = 0; mi < 2; mi++) {
#pragma unroll
            for (int h = 0; h < 2; h++) {
                int row = m0 + wm * 32 + mi * 16 + qr + h * 8;
                float v0 = fmaf((float)accH[mi][ni][h * 2 + 0], e10,
                          fmaf((float)accL[mi][ni][h * 2 + 0], e20, b0v));
                float v1 = fmaf((float)accH[mi][ni][h * 2 + 1], e11,
                          fmaf((float)accL[mi][ni][h * 2 + 1], e21, b1v));
                float* cp = C + (size_t)row * N + n;
                if (has2) *reinterpret_cast<float2*>(cp) = make_float2(v0, v1);
                else      cp[0] = v0;
            }
        }
    }
}

// ---------------------------------------------------------------------------
// log-softmax over rows of [ROWS, OUTDIM], in place
// ---------------------------------------------------------------------------
__global__ void __launch_bounds__(256) logsoftmax_kernel(float* __restrict__ out) {
    __shared__ float sv[OUTDIM];
    __shared__ float red[9];
    const int tid = threadIdx.x, lane = tid & 31, warp = tid >> 5;
    float* p = out + (size_t)blockIdx.x * OUTDIM;

    float mx = -3.4e38f;
    for (int i = tid; i < OUTDIM; i += 256) { float v = p[i]; sv[i] = v; mx = fmaxf(mx, v); }
#pragma unroll
    for (int o = 16; o; o >>= 1) mx = fmaxf(mx, __shfl_xor_sync(0xffffffffu, mx, o));
    if (lane == 0) red[warp] = mx;
    __syncthreads();
    if (warp == 0) {
        float v = (lane < 8) ? red[lane] : -3.4e38f;
#pragma unroll
        for (int o = 4; o; o >>= 1) v = fmaxf(v, __shfl_xor_sync(0xffffffffu, v, o));
        if (lane == 0) red[8] = v;
    }
    __syncthreads();
    mx = red[8];

    float s = 0.0f;
    for (int i = tid; i < OUTDIM; i += 256) s += expf(sv[i] - mx);
#pragma unroll
    for (int o = 16; o; o >>= 1) s += __shfl_xor_sync(0xffffffffu, s, o);
    __syncthreads();
    if (lane == 0) red[warp] = s;
    __syncthreads();
    if (warp == 0) {
        float v = (lane < 8) ? red[lane] : 0.0f;
#pragma unroll
        for (int o = 4; o; o >>= 1) v += __shfl_xor_sync(0xffffffffu, v, o);
        if (lane == 0) red[8] = v;
    }
    __syncthreads();
    float lse = mx + logf(red[8]);
    for (int i = tid; i < OUTDIM; i += 256) p[i] = sv[i] - lse;
}

// ---------------------------------------------------------------------------
// Launch sequence
// ---------------------------------------------------------------------------
extern "C" void kernel_launch(void* const* d_in, const int* in_sizes, int n_in,
                              void* d_out, int out_size) {
    const float* xs   = (const float*)d_in[0];   // [500,64,440]
    const float* W0   = (const float*)d_in[1];   // [1024,440]
    const float* Ws   = (const float*)d_in[2];   // [3,1024,1024]
    const float* taus = (const float*)d_in[3];   // [4,1024]
    const float* bng  = (const float*)d_in[4];   // [4,1024]
    const float* bnb  = (const float*)d_in[5];   // [4,1024]
    const float* Wf   = (const float*)d_in[6];   // [1944,1024]
    const float* fg   = (const float*)d_in[7];   // [1944]
    const float* fb   = (const float*)d_in[8];   // [1944]
    float* out = (float*)d_out;

    void* p;
    cudaGetSymbolAddress(&p, g_act);  int8_t* act  = (int8_t*)p;
    cudaGetSymbolAddress(&p, g_ws);   float*  ws   = (float*)p;
    cudaGetSymbolAddress(&p, g_W0q1); int8_t* w0q1 = (int8_t*)p;
    cudaGetSymbolAddress(&p, g_W0q2); int8_t* w0q2 = (int8_t*)p;
    cudaGetSymbolAddress(&p, g_Wsq1); int8_t* wsq1 = (int8_t*)p;
    cudaGetSymbolAddress(&p, g_Wsq2); int8_t* wsq2 = (int8_t*)p;
    cudaGetSymbolAddress(&p, g_Wfq1); int8_t* wfq1 = (int8_t*)p;
    cudaGetSymbolAddress(&p, g_Wfq2); int8_t* wfq2 = (int8_t*)p;
    cudaGetSymbolAddress(&p, g_s1);   float*  s1   = (float*)p;
    cudaGetSymbolAddress(&p, g_s2);   float*  s2   = (float*)p;

    cudaFuncSetAttribute(gemm_bn_s8, cudaFuncAttributeMaxDynamicSharedMemorySize, GEMM_SMEM);

    // per-row dual int8 quantization of all weights
    quantize_rows<<<HID, 256>>>(W0, w0q1, w0q2, s1, s2, INDIM, INPAD);
    quantize_rows<<<3 * HID, 256>>>(Ws, wsq1, wsq2, s1 + 1024, s2 + 1024, HID, HID);
    quantize_rows<<<OUTDIM, 256>>>(Wf, wfq1, wfq2, s1 + 4096, s2 + 4096, HID, HID);

    // input FSQ scan -> act [32000, 448] int8
    input_scan_kernel<<<(BATCH * INPAD + 127) / 128, 128>>>(xs, act);

    dim3 gh(ROWS / BM, HID / BN);   // (250, 8)

    // layer 0
    gemm_bn_s8<<<gh, 256, GEMM_SMEM>>>(act, w0q1, w0q2, ws, HID, INPAD,
                                       s1, s2, bng, bnb);
    lif_scan_kernel<<<(BATCH * HID) / 128, 128>>>(ws, taus, act);

    // layers 1..3
    for (int l = 1; l < 4; l++) {
        gemm_bn_s8<<<gh, 256, GEMM_SMEM>>>(
            act, wsq1 + (size_t)(l - 1) * HID * HID, wsq2 + (size_t)(l - 1) * HID * HID,
            ws, HID, HID, s1 + 1024 + (l - 1) * HID, s2 + 1024 + (l - 1) * HID,
            bng + l * HID, bnb + l * HID);
        lif_scan_kernel<<<(BATCH * HID) / 128, 128>>>(ws, taus + l * HID, act);
    }

    // final projection -> d_out [32000, 1944] fp32
    dim3 gf(ROWS / BM, (OUTDIM + BN - 1) / BN);  // (250, 16)
    gemm_bn_s8<<<gf, 256, GEMM_SMEM>>>(act, wfq1, wfq2, out, OUTDIM, HID,
                                       s1 + 4096, s2 + 4096, fg, fb);

    // in-place log-softmax per row
    logsoftmax_kernel<<<ROWS, 256>>>(out);
}

// round 11
// speedup vs baseline: 2.9290x; 2.9290x over previous
#include <cuda_runtime.h>
#include <cuda_bf16.h>
#include <cuda_fp16.h>
#include <cstdint>

#define TSTEPS 500
#define BATCH  64
#define INDIM  440
#define INPAD  448
#define HID    1024
#define OUTDIM 1944
#define ROWS   (TSTEPS * BATCH)   // 32000

// ---------------------------------------------------------------------------
// Scratch (static device globals; no runtime allocation allowed)
// ---------------------------------------------------------------------------
__device__ __align__(16) __nv_bfloat16 g_actB[(size_t)ROWS * HID];  // spikes (bf16, exact)
__device__ __align__(16) __half        g_actH[(size_t)ROWS * HID];  // spikes (fp16, exact)
__device__ __align__(16) float         g_ws  [(size_t)ROWS * HID];  // pre-scan dense outputs
__device__ __align__(16) __nv_bfloat16 g_W0hi[HID * INPAD];
__device__ __align__(16) __nv_bfloat16 g_W0lo[HID * INPAD];
__device__ __align__(16) __nv_bfloat16 g_W1hi[HID * HID];
__device__ __align__(16) __nv_bfloat16 g_W1lo[HID * HID];
__device__ __align__(16) __half        g_W23h[2 * HID * HID];       // layers 2,3 fp16
__device__ __align__(16) __half        g_Wfh [OUTDIM * HID];        // final fp16

// ---------------------------------------------------------------------------
// Weight split: w -> bf16 hi + bf16 lo (residual), with K padding zeroed
// ---------------------------------------------------------------------------
__global__ void split_weights_kernel(const float* __restrict__ W,
                                     __nv_bfloat16* __restrict__ hi,
                                     __nv_bfloat16* __restrict__ lo,
                                     int rows, int cols, int colsPad) {
    long long idx = (long long)blockIdx.x * blockDim.x + threadIdx.x;
    long long total = (long long)rows * colsPad;
    if (idx >= total) return;
    int r = (int)(idx / colsPad);
    int c = (int)(idx % colsPad);
    float w = (c < cols) ? W[(long long)r * cols + c] : 0.0f;
    __nv_bfloat16 h = __float2bfloat16(w);
    hi[idx] = h;
    lo[idx] = __float2bfloat16(w - __bfloat162float(h));
}

// float -> fp16 (round to nearest), contiguous
__global__ void to_half_kernel(const float* __restrict__ W, __half* __restrict__ H,
                               long long total) {
    long long idx = (long long)blockIdx.x * blockDim.x + threadIdx.x;
    if (idx < total) H[idx] = __float2half_rn(W[idx]);
}

// ---------------------------------------------------------------------------
// Input FSQ scan: vmem += x; q = clip(rint(vmem),0,7); out=q; vmem -= q
// One thread per (b, i) channel, sequential over T (8-deep load batching).
// ---------------------------------------------------------------------------
__global__ void __launch_bounds__(128)
input_scan_kernel(const float* __restrict__ xs, __nv_bfloat16* __restrict__ act) {
    int tid = blockIdx.x * blockDim.x + threadIdx.x;
    if (tid >= BATCH * INPAD) return;
    int b = tid / INPAD, i = tid % INPAD;
    __nv_bfloat16* op = act + (size_t)b * INPAD + i;
    const int strideO = BATCH * INPAD;
    if (i >= INDIM) {
        __nv_bfloat16 z = __float2bfloat16(0.0f);
        for (int t = 0; t < TSTEPS; t++) op[t * strideO] = z;
        return;
    }
    const float* xp = xs + (size_t)b * INDIM + i;
    const int strideX = BATCH * INDIM;
    float vmem = 0.0f;
#define ISTEP(X, TT) { vmem = __fadd_rn(vmem, (X)); \
        float q = fminf(7.0f, fmaxf(0.0f, rintf(vmem))); \
        op[(TT) * strideO] = __float2bfloat16(q); \
        vmem = __fsub_rn(vmem, q); }
    int t = 0;
    for (; t + 8 <= TSTEPS; t += 8) {
        float x[8];
#pragma unroll
        for (int j = 0; j < 8; j++) x[j] = xp[(t + j) * strideX];
#pragma unroll
        for (int j = 0; j < 8; j++) ISTEP(x[j], t + j)
    }
    for (; t < TSTEPS; t++) { float x = xp[t * strideX]; ISTEP(x, t) }
#undef ISTEP
}

// ---------------------------------------------------------------------------
// LIF scan: syn = w + tau*syn; vmem += syn; q = clip(rint(vmem),0,7); vmem -= q
// One thread per (b, h) channel; output dtype templated (bf16 or fp16).
// ---------------------------------------------------------------------------
template <typename TO>
__device__ __forceinline__ TO cvt_spike(float q);
template <> __device__ __forceinline__ __nv_bfloat16 cvt_spike<__nv_bfloat16>(float q) {
    return __float2bfloat16(q);
}
template <> __device__ __forceinline__ __half cvt_spike<__half>(float q) {
    return __float2half_rn(q);
}

template <typename TO>
__global__ void __launch_bounds__(128)
lif_scan_kernel(const float* __restrict__ ws, const float* __restrict__ taus,
                TO* __restrict__ act) {
    int tid = blockIdx.x * blockDim.x + threadIdx.x;
    if (tid >= BATCH * HID) return;
    int b = tid / HID, h = tid % HID;
    float tau = taus[h];
    const float* wp = ws + (size_t)b * HID + h;
    TO* op = act + (size_t)b * HID + h;
    const int stride = BATCH * HID;
    float syn = 0.0f, vmem = 0.0f;
#define LSTEP(W, TT) { syn = __fadd_rn((W), __fmul_rn(tau, syn)); \
        vmem = __fadd_rn(vmem, syn); \
        float q = fminf(7.0f, fmaxf(0.0f, rintf(vmem))); \
        op[(TT) * stride] = cvt_spike<TO>(q); \
        vmem = __fsub_rn(vmem, q); }
    int t = 0;
    for (; t + 8 <= TSTEPS; t += 8) {
        float w[8];
#pragma unroll
        for (int j = 0; j < 8; j++) w[j] = wp[(t + j) * stride];
#pragma unroll
        for (int j = 0; j < 8; j++) LSTEP(w[j], t + j)
    }
    for (; t < TSTEPS; t++) { float w = wp[t * stride]; LSTEP(w, t) }
#undef LSTEP
}

// ---------------------------------------------------------------------------
// GEMM: C[M,N] = A[M,K] * (Bhi [+ Blo])[N,K]^T, fused BN epilogue.
// mma.sync m16n8k16 (bf16 or f16 by template), 128x128x32 CTA tile,
// 3-stage cp.async pipeline.  (Proven R6 body; dtype templated.)
// ---------------------------------------------------------------------------
#define BM 128
#define BN 128
#define BK 32
#define GSTAGES 3
#define LDS_ROW 40                          // 16-bit elems per smem row (32 + 8 pad)
#define STAGE_ONE_BYTES (128 * LDS_ROW * 2) // 10240 per matrix

__device__ __forceinline__ void cp_async16(uint32_t dst, const void* src, bool pred) {
    int bytes = pred ? 16 : 0;
    asm volatile("cp.async.cg.shared.global [%0], [%1], 16, %2;\n"
                 :: "r"(dst), "l"(src), "r"(bytes));
}
__device__ __forceinline__ void ldm4(uint32_t* r, uint32_t addr) {
    asm volatile("ldmatrix.sync.aligned.m8n8.x4.shared.b16 {%0,%1,%2,%3}, [%4];\n"
                 : "=r"(r[0]), "=r"(r[1]), "=r"(r[2]), "=r"(r[3]) : "r"(addr));
}
template <bool F16>
__device__ __forceinline__ void mma16816(float* c, const uint32_t* a, uint32_t b0, uint32_t b1) {
    if constexpr (F16) {
        asm volatile("mma.sync.aligned.m16n8k16.row.col.f32.f16.f16.f32 "
                     "{%0,%1,%2,%3}, {%4,%5,%6,%7}, {%8,%9}, {%0,%1,%2,%3};\n"
                     : "+f"(c[0]), "+f"(c[1]), "+f"(c[2]), "+f"(c[3])
                     : "r"(a[0]), "r"(a[1]), "r"(a[2]), "r"(a[3]), "r"(b0), "r"(b1));
    } else {
        asm volatile("mma.sync.aligned.m16n8k16.row.col.f32.bf16.bf16.f32 "
                     "{%0,%1,%2,%3}, {%4,%5,%6,%7}, {%8,%9}, {%0,%1,%2,%3};\n"
                     : "+f"(c[0]), "+f"(c[1]), "+f"(c[2]), "+f"(c[3])
                     : "r"(a[0]), "r"(a[1]), "r"(a[2]), "r"(a[3]), "r"(b0), "r"(b1));
    }
}

template <bool F16, bool HAS_LO>
__global__ void __launch_bounds__(256)
gemm_bn_kernel(const uint16_t* __restrict__ A,
               const uint16_t* __restrict__ Bhi,
               const uint16_t* __restrict__ Blo,
               float* __restrict__ C,
               int N, int K,
               const float* __restrict__ gamma,
               const float* __restrict__ beta) {
    extern __shared__ __align__(16) uint16_t smem_buf[];
    constexpr uint32_t NTILES = HAS_LO ? 3u : 2u;
    constexpr uint32_t STAGE_BYTES = NTILES * STAGE_ONE_BYTES;
    const int tid = threadIdx.x;
    const int lane = tid & 31, warp = tid >> 5;
    const int wm = warp >> 1;      // 0..3  -> 32 rows of M each
    const int wn = warp & 1;       // 0..1  -> 64 cols of N each
    const int m0 = blockIdx.x * BM;
    const int n0 = blockIdx.y * BN;
    const int KT = K / BK;
    const uint32_t sbase = (uint32_t)__cvta_generic_to_shared(smem_buf);

    const int lm   = lane & 7;
    const int mat  = lane >> 3;
    const int roff = ((mat & 1) << 3) | lm;   // +0 / +8 row
    const int koff = (mat >> 1) << 3;         // +0 / +8 col (elems)

    float acc[2][8][4] = {};

    auto issue_stage = [&](int kt, int s) {
        if (kt < KT) {
            const int kk = kt * BK;
            const uint32_t sA  = sbase + s * STAGE_BYTES;
            const uint32_t sBh = sA + STAGE_ONE_BYTES;
            const uint32_t sBl = sBh + STAGE_ONE_BYTES;
#pragma unroll
            for (int i = 0; i < 2; i++) {
                int c = tid + i * 256;
                int r = c >> 2, col = c & 3;
                uint32_t dst = sA + (uint32_t)(r * LDS_ROW + col * 8) * 2;
                cp_async16(dst, A + (size_t)(m0 + r) * K + kk + col * 8, true);
            }
#pragma unroll
            for (int i = 0; i < 2; i++) {
                int c = tid + i * 256;
                int r = c >> 2, col = c & 3;
                bool pred = (n0 + r) < N;
                int rr = pred ? (n0 + r) : 0;
                uint32_t dst = sBh + (uint32_t)(r * LDS_ROW + col * 8) * 2;
                cp_async16(dst, Bhi + (size_t)rr * K + kk + col * 8, pred);
                if (HAS_LO) {
                    uint32_t dstl = sBl + (uint32_t)(r * LDS_ROW + col * 8) * 2;
                    cp_async16(dstl, Blo + (size_t)rr * K + kk + col * 8, pred);
                }
            }
        }
        asm volatile("cp.async.commit_group;\n" ::);
    };

    auto compute_stage = [&](int s) {
        const uint32_t aB  = sbase + s * STAGE_BYTES;
        const uint32_t bhB = aB + STAGE_ONE_BYTES;
        const uint32_t blB = bhB + STAGE_ONE_BYTES;
#pragma unroll
        for (int k16 = 0; k16 < 2; k16++) {
            uint32_t afr[2][4];
#pragma unroll
            for (int mi = 0; mi < 2; mi++)
                ldm4(afr[mi], aB + (uint32_t)((wm * 32 + mi * 16 + roff) * LDS_ROW + k16 * 16 + koff) * 2);
#pragma unroll
            for (int nj = 0; nj < 4; nj++) {
                uint32_t boff = (uint32_t)((wn * 64 + nj * 16 + roff) * LDS_ROW + k16 * 16 + koff) * 2;
                uint32_t bfr[4];
                ldm4(bfr, bhB + boff);
                mma16816<F16>(acc[0][2 * nj + 0], afr[0], bfr[0], bfr[2]);
                mma16816<F16>(acc[1][2 * nj + 0], afr[1], bfr[0], bfr[2]);
                mma16816<F16>(acc[0][2 * nj + 1], afr[0], bfr[1], bfr[3]);
                mma16816<F16>(acc[1][2 * nj + 1], afr[1], bfr[1], bfr[3]);
                if (HAS_LO) {
                    uint32_t lfr[4];
                    ldm4(lfr, blB + boff);
                    mma16816<F16>(acc[0][2 * nj + 0], afr[0], lfr[0], lfr[2]);
                    mma16816<F16>(acc[1][2 * nj + 0], afr[1], lfr[0], lfr[2]);
                    mma16816<F16>(acc[0][2 * nj + 1], afr[0], lfr[1], lfr[3]);
                    mma16816<F16>(acc[1][2 * nj + 1], afr[1], lfr[1], lfr[3]);
                }
            }
        }
    };

#pragma unroll
    for (int s = 0; s < GSTAGES - 1; s++) issue_stage(s, s);

    for (int kt = 0; kt < KT; kt++) {
        asm volatile("cp.async.wait_group 1;\n" ::);
        __syncthreads();
        compute_stage(kt % GSTAGES);
        issue_stage(kt + GSTAGES - 1, (kt + GSTAGES - 1) % GSTAGES);
    }
    asm volatile("cp.async.wait_group 0;\n" ::);

    // Epilogue: BN (x * gamma/sqrt(1+eps) + beta), write fp32
    const float inv = rsqrtf(1.0f + 1e-5f);
    const int qr = lane >> 2;
    const int qc = (lane & 3) << 1;
#pragma unroll
    for (int ni = 0; ni < 8; ni++) {
        int n = n0 + wn * 64 + ni * 8 + qc;
        if (n >= N) continue;
        float g0 = gamma[n] * inv, b0 = beta[n];
        bool has2 = (n + 1 < N);
        float g1 = has2 ? gamma[n + 1] * inv : 0.0f;
        float b1 = has2 ? beta[n + 1] : 0.0f;
#pragma unroll
        for (int mi = 0; mi < 2; mi++) {
#pragma unroll
            for (int h = 0; h < 2; h++) {
                int row = m0 + wm * 32 + mi * 16 + qr + h * 8;
                float v0 = fmaf(acc[mi][ni][h * 2 + 0], g0, b0);
                float v1 = fmaf(acc[mi][ni][h * 2 + 1], g1, b1);
                float* cp = C + (size_t)row * N + n;
                if (has2) *reinterpret_cast<float2*>(cp) = make_float2(v0, v1);
                else      cp[0] = v0;
            }
        }
    }
}

#define SMEM_DUAL (GSTAGES * 3 * STAGE_ONE_BYTES)  // 92160
#define SMEM_SGL  (GSTAGES * 2 * STAGE_ONE_BYTES)  // 61440

// ---------------------------------------------------------------------------
// log-softmax over rows of [ROWS, OUTDIM], in place
// ---------------------------------------------------------------------------
__global__ void __launch_bounds__(256) logsoftmax_kernel(float* __restrict__ out) {
    __shared__ float sv[OUTDIM];
    __shared__ float red[9];
    const int tid = threadIdx.x, lane = tid & 31, warp = tid >> 5;
    float* p = out + (size_t)blockIdx.x * OUTDIM;

    float mx = -3.4e38f;
    for (int i = tid; i < OUTDIM; i += 256) { float v = p[i]; sv[i] = v; mx = fmaxf(mx, v); }
#pragma unroll
    for (int o = 16; o; o >>= 1) mx = fmaxf(mx, __shfl_xor_sync(0xffffffffu, mx, o));
    if (lane == 0) red[warp] = mx;
    __syncthreads();
    if (warp == 0) {
        float v = (lane < 8) ? red[lane] : -3.4e38f;
#pragma unroll
        for (int o = 4; o; o >>= 1) v = fmaxf(v, __shfl_xor_sync(0xffffffffu, v, o));
        if (lane == 0) red[8] = v;
    }
    __syncthreads();
    mx = red[8];

    float s = 0.0f;
    for (int i = tid; i < OUTDIM; i += 256) s += expf(sv[i] - mx);
#pragma unroll
    for (int o = 16; o; o >>= 1) s += __shfl_xor_sync(0xffffffffu, s, o);
    __syncthreads();
    if (lane == 0) red[warp] = s;
    __syncthreads();
    if (warp == 0) {
        float v = (lane < 8) ? red[lane] : 0.0f;
#pragma unroll
        for (int o = 4; o; o >>= 1) v += __shfl_xor_sync(0xffffffffu, v, o);
        if (lane == 0) red[8] = v;
    }
    __syncthreads();
    float lse = mx + logf(red[8]);
    for (int i = tid; i < OUTDIM; i += 256) p[i] = sv[i] - lse;
}

// ---------------------------------------------------------------------------
// Launch sequence
// ---------------------------------------------------------------------------
extern "C" void kernel_launch(void* const* d_in, const int* in_sizes, int n_in,
                              void* d_out, int out_size) {
    const float* xs   = (const float*)d_in[0];   // [500,64,440]
    const float* W0   = (const float*)d_in[1];   // [1024,440]
    const float* Ws   = (const float*)d_in[2];   // [3,1024,1024]
    const float* taus = (const float*)d_in[3];   // [4,1024]
    const float* bng  = (const float*)d_in[4];   // [4,1024]
    const float* bnb  = (const float*)d_in[5];   // [4,1024]
    const float* Wf   = (const float*)d_in[6];   // [1944,1024]
    const float* fg   = (const float*)d_in[7];   // [1944]
    const float* fb   = (const float*)d_in[8];   // [1944]
    float* out = (float*)d_out;

    void* p;
    cudaGetSymbolAddress(&p, g_actB); uint16_t* actB = (uint16_t*)p;
    cudaGetSymbolAddress(&p, g_actH); uint16_t* actH = (uint16_t*)p;
    cudaGetSymbolAddress(&p, g_ws);   float*    ws   = (float*)p;
    cudaGetSymbolAddress(&p, g_W0hi); uint16_t* w0hi = (uint16_t*)p;
    cudaGetSymbolAddress(&p, g_W0lo); uint16_t* w0lo = (uint16_t*)p;
    cudaGetSymbolAddress(&p, g_W1hi); uint16_t* w1hi = (uint16_t*)p;
    cudaGetSymbolAddress(&p, g_W1lo); uint16_t* w1lo = (uint16_t*)p;
    cudaGetSymbolAddress(&p, g_W23h); uint16_t* w23h = (uint16_t*)p;
    cudaGetSymbolAddress(&p, g_Wfh);  uint16_t* wfh  = (uint16_t*)p;

    cudaFuncSetAttribute((const void*)gemm_bn_kernel<false, true>,
                         cudaFuncAttributeMaxDynamicSharedMemorySize, SMEM_DUAL);
    cudaFuncSetAttribute((const void*)gemm_bn_kernel<true, false>,
                         cudaFuncAttributeMaxDynamicSharedMemorySize, SMEM_SGL);

    // --- weight preparation (idempotent) ---
    split_weights_kernel<<<(HID * INPAD + 255) / 256, 256>>>(
        W0, (__nv_bfloat16*)w0hi, (__nv_bfloat16*)w0lo, HID, INDIM, INPAD);
    split_weights_kernel<<<(HID * HID + 255) / 256, 256>>>(
        Ws, (__nv_bfloat16*)w1hi, (__nv_bfloat16*)w1lo, HID, HID, HID);
    to_half_kernel<<<(2 * HID * HID + 255) / 256, 256>>>(
        Ws + (size_t)HID * HID, (__half*)w23h, (long long)2 * HID * HID);
    to_half_kernel<<<((long long)OUTDIM * HID + 255) / 256, 256>>>(
        Wf, (__half*)wfh, (long long)OUTDIM * HID);

    // --- input FSQ scan -> actB [32000, 448] bf16 ---
    input_scan_kernel<<<(BATCH * INPAD + 127) / 128, 128>>>(xs, (__nv_bfloat16*)actB);

    dim3 gh(ROWS / BM, HID / BN);   // (250, 8)

    // layer 0 (bf16 hi+lo)
    gemm_bn_kernel<false, true><<<gh, 256, SMEM_DUAL>>>(
        actB, w0hi, w0lo, ws, HID, INPAD, bng, bnb);
    lif_scan_kernel<__nv_bfloat16><<<(BATCH * HID) / 128, 128>>>(
        ws, taus, (__nv_bfloat16*)actB);

    // layer 1 (bf16 hi+lo) -> output spikes in fp16 for layer 2
    gemm_bn_kernel<false, true><<<gh, 256, SMEM_DUAL>>>(
        actB, w1hi, w1lo, ws, HID, HID, bng + HID, bnb + HID);
    lif_scan_kernel<__half><<<(BATCH * HID) / 128, 128>>>(
        ws, taus + HID, (__half*)actH);

    // layers 2,3 (fp16 single-pass)
    for (int l = 2; l < 4; l++) {
        gemm_bn_kernel<true, false><<<gh, 256, SMEM_SGL>>>(
            actH, w23h + (size_t)(l - 2) * HID * HID, nullptr,
            ws, HID, HID, bng + l * HID, bnb + l * HID);
        lif_scan_kernel<__half><<<(BATCH * HID) / 128, 128>>>(
            ws, taus + l * HID, (__half*)actH);
    }

    // final projection (fp16 single) -> d_out [32000, 1944] fp32
    dim3 gf(ROWS / BM, (OUTDIM + BN - 1) / BN);  // (250, 16)
    gemm_bn_kernel<true, false><<<gf, 256, SMEM_SGL>>>(
        actH, wfh, nullptr, out, OUTDIM, HID, fg, fb);

    // in-place log-softmax per row
    logsoftmax_kernel<<<ROWS, 256>>>(out);
}

// round 13
// speedup vs baseline: 3.1681x; 1.0816x over previous
#include <cuda_runtime.h>
#include <cuda_bf16.h>
#include <cuda_fp16.h>
#include <cstdint>

#define TSTEPS 500
#define BATCH  64
#define INDIM  440
#define INPAD  448
#define HID    1024
#define OUTDIM 1944
#define ROWS   (TSTEPS * BATCH)   // 32000

// ---------------------------------------------------------------------------
// Scratch (static device globals; no runtime allocation allowed)
// ---------------------------------------------------------------------------
__device__ __align__(16) __nv_bfloat16 g_actB[(size_t)ROWS * HID];  // spikes (bf16, exact)
__device__ __align__(16) __half        g_actH[(size_t)ROWS * HID];  // spikes (fp16, exact)
__device__ __align__(16) float         g_ws  [(size_t)ROWS * HID];  // pre-scan dense outputs
__device__ __align__(16) __nv_bfloat16 g_W0hi[HID * INPAD];
__device__ __align__(16) __nv_bfloat16 g_W0lo[HID * INPAD];
__device__ __align__(16) __half        g_Wsh [3 * HID * HID];       // layers 1,2,3 fp16
__device__ __align__(16) __half        g_Wfh [OUTDIM * HID];        // final fp16

// ---------------------------------------------------------------------------
// Weight split: w -> bf16 hi + bf16 lo (residual), with K padding zeroed
// ---------------------------------------------------------------------------
__global__ void split_weights_kernel(const float* __restrict__ W,
                                     __nv_bfloat16* __restrict__ hi,
                                     __nv_bfloat16* __restrict__ lo,
                                     int rows, int cols, int colsPad) {
    long long idx = (long long)blockIdx.x * blockDim.x + threadIdx.x;
    long long total = (long long)rows * colsPad;
    if (idx >= total) return;
    int r = (int)(idx / colsPad);
    int c = (int)(idx % colsPad);
    float w = (c < cols) ? W[(long long)r * cols + c] : 0.0f;
    __nv_bfloat16 h = __float2bfloat16(w);
    hi[idx] = h;
    lo[idx] = __float2bfloat16(w - __bfloat162float(h));
}

// float -> fp16 (round to nearest), contiguous
__global__ void to_half_kernel(const float* __restrict__ W, __half* __restrict__ H,
                               long long total) {
    long long idx = (long long)blockIdx.x * blockDim.x + threadIdx.x;
    if (idx < total) H[idx] = __float2half_rn(W[idx]);
}

// ---------------------------------------------------------------------------
// Input FSQ scan: vmem += x; q = clip(rint(vmem),0,7); out=q; vmem -= q
// One thread per (b, i) channel, sequential over T (8-deep load batching).
// ---------------------------------------------------------------------------
__global__ void __launch_bounds__(128)
input_scan_kernel(const float* __restrict__ xs, __nv_bfloat16* __restrict__ act) {
    int tid = blockIdx.x * blockDim.x + threadIdx.x;
    if (tid >= BATCH * INPAD) return;
    int b = tid / INPAD, i = tid % INPAD;
    __nv_bfloat16* op = act + (size_t)b * INPAD + i;
    const int strideO = BATCH * INPAD;
    if (i >= INDIM) {
        __nv_bfloat16 z = __float2bfloat16(0.0f);
        for (int t = 0; t < TSTEPS; t++) op[t * strideO] = z;
        return;
    }
    const float* xp = xs + (size_t)b * INDIM + i;
    const int strideX = BATCH * INDIM;
    float vmem = 0.0f;
#define ISTEP(X, TT) { vmem = __fadd_rn(vmem, (X)); \
        float q = fminf(7.0f, fmaxf(0.0f, rintf(vmem))); \
        op[(TT) * strideO] = __float2bfloat16(q); \
        vmem = __fsub_rn(vmem, q); }
    int t = 0;
    for (; t + 8 <= TSTEPS; t += 8) {
        float x[8];
#pragma unroll
        for (int j = 0; j < 8; j++) x[j] = xp[(t + j) * strideX];
#pragma unroll
        for (int j = 0; j < 8; j++) ISTEP(x[j], t + j)
    }
    for (; t < TSTEPS; t++) { float x = xp[t * strideX]; ISTEP(x, t) }
#undef ISTEP
}

// ---------------------------------------------------------------------------
// LIF scan: syn = w + tau*syn; vmem += syn; q = clip(rint(vmem),0,7); vmem -= q
// One thread per (b, h) channel; output dtype templated (bf16 or fp16).
// ---------------------------------------------------------------------------
template <typename TO>
__device__ __forceinline__ TO cvt_spike(float q);
template <> __device__ __forceinline__ __nv_bfloat16 cvt_spike<__nv_bfloat16>(float q) {
    return __float2bfloat16(q);
}
template <> __device__ __forceinline__ __half cvt_spike<__half>(float q) {
    return __float2half_rn(q);
}

template <typename TO>
__global__ void __launch_bounds__(128)
lif_scan_kernel(const float* __restrict__ ws, const float* __restrict__ taus,
                TO* __restrict__ act) {
    int tid = blockIdx.x * blockDim.x + threadIdx.x;
    if (tid >= BATCH * HID) return;
    int b = tid / HID, h = tid % HID;
    float tau = taus[h];
    const float* wp = ws + (size_t)b * HID + h;
    TO* op = act + (size_t)b * HID + h;
    const int stride = BATCH * HID;
    float syn = 0.0f, vmem = 0.0f;
#define LSTEP(W, TT) { syn = __fadd_rn((W), __fmul_rn(tau, syn)); \
        vmem = __fadd_rn(vmem, syn); \
        float q = fminf(7.0f, fmaxf(0.0f, rintf(vmem))); \
        op[(TT) * stride] = cvt_spike<TO>(q); \
        vmem = __fsub_rn(vmem, q); }
    int t = 0;
    for (; t + 8 <= TSTEPS; t += 8) {
        float w[8];
#pragma unroll
        for (int j = 0; j < 8; j++) w[j] = wp[(t + j) * stride];
#pragma unroll
        for (int j = 0; j < 8; j++) LSTEP(w[j], t + j)
    }
    for (; t < TSTEPS; t++) { float w = wp[t * stride]; LSTEP(w, t) }
#undef LSTEP
}

// ---------------------------------------------------------------------------
// GEMM: C[M,N] = A[M,K] * (Bhi [+ Blo])[N,K]^T, fused BN epilogue.
// mma.sync m16n8k16 (bf16 or f16 by template), 128x128x32 CTA tile,
// 3-stage cp.async pipeline.
// ---------------------------------------------------------------------------
#define BM 128
#define BN 128
#define BK 32
#define GSTAGES 3
#define LDS_ROW 40                          // 16-bit elems per smem row (32 + 8 pad)
#define STAGE_ONE_BYTES (128 * LDS_ROW * 2) // 10240 per matrix

__device__ __forceinline__ void cp_async16(uint32_t dst, const void* src, bool pred) {
    int bytes = pred ? 16 : 0;
    asm volatile("cp.async.cg.shared.global [%0], [%1], 16, %2;\n"
                 :: "r"(dst), "l"(src), "r"(bytes));
}
__device__ __forceinline__ void ldm4(uint32_t* r, uint32_t addr) {
    asm volatile("ldmatrix.sync.aligned.m8n8.x4.shared.b16 {%0,%1,%2,%3}, [%4];\n"
                 : "=r"(r[0]), "=r"(r[1]), "=r"(r[2]), "=r"(r[3]) : "r"(addr));
}
template <bool F16>
__device__ __forceinline__ void mma16816(float* c, const uint32_t* a, uint32_t b0, uint32_t b1) {
    if constexpr (F16) {
        asm volatile("mma.sync.aligned.m16n8k16.row.col.f32.f16.f16.f32 "
                     "{%0,%1,%2,%3}, {%4,%5,%6,%7}, {%8,%9}, {%0,%1,%2,%3};\n"
                     : "+f"(c[0]), "+f"(c[1]), "+f"(c[2]), "+f"(c[3])
                     : "r"(a[0]), "r"(a[1]), "r"(a[2]), "r"(a[3]), "r"(b0), "r"(b1));
    } else {
        asm volatile("mma.sync.aligned.m16n8k16.row.col.f32.bf16.bf16.f32 "
                     "{%0,%1,%2,%3}, {%4,%5,%6,%7}, {%8,%9}, {%0,%1,%2,%3};\n"
                     : "+f"(c[0]), "+f"(c[1]), "+f"(c[2]), "+f"(c[3])
                     : "r"(a[0]), "r"(a[1]), "r"(a[2]), "r"(a[3]), "r"(b0), "r"(b1));
    }
}

template <bool F16, bool HAS_LO>
__global__ void __launch_bounds__(256)
gemm_bn_kernel(const uint16_t* __restrict__ A,
               const uint16_t* __restrict__ Bhi,
               const uint16_t* __restrict__ Blo,
               float* __restrict__ C,
               int N, int K,
               const float* __restrict__ gamma,
               const float* __restrict__ beta) {
    extern __shared__ __align__(16) uint16_t smem_buf[];
    constexpr uint32_t NTILES = HAS_LO ? 3u : 2u;
    constexpr uint32_t STAGE_BYTES = NTILES * STAGE_ONE_BYTES;
    const int tid = threadIdx.x;
    const int lane = tid & 31, warp = tid >> 5;
    const int wm = warp >> 1;      // 0..3  -> 32 rows of M each
    const int wn = warp & 1;       // 0..1  -> 64 cols of N each
    const int m0 = blockIdx.x * BM;
    const int n0 = blockIdx.y * BN;
    const int KT = K / BK;
    const uint32_t sbase = (uint32_t)__cvta_generic_to_shared(smem_buf);

    const int lm   = lane & 7;
    const int mat  = lane >> 3;
    const int roff = ((mat & 1) << 3) | lm;   // +0 / +8 row
    const int koff = (mat >> 1) << 3;         // +0 / +8 col (elems)

    float acc[2][8][4] = {};

    auto issue_stage = [&](int kt, int s) {
        if (kt < KT) {
            const int kk = kt * BK;
            const uint32_t sA  = sbase + s * STAGE_BYTES;
            const uint32_t sBh = sA + STAGE_ONE_BYTES;
            const uint32_t sBl = sBh + STAGE_ONE_BYTES;
#pragma unroll
            for (int i = 0; i < 2; i++) {
                int c = tid + i * 256;
                int r = c >> 2, col = c & 3;
                uint32_t dst = sA + (uint32_t)(r * LDS_ROW + col * 8) * 2;
                cp_async16(dst, A + (size_t)(m0 + r) * K + kk + col * 8, true);
            }
#pragma unroll
            for (int i = 0; i < 2; i++) {
                int c = tid + i * 256;
                int r = c >> 2, col = c & 3;
                bool pred = (n0 + r) < N;
                int rr = pred ? (n0 + r) : 0;
                uint32_t dst = sBh + (uint32_t)(r * LDS_ROW + col * 8) * 2;
                cp_async16(dst, Bhi + (size_t)rr * K + kk + col * 8, pred);
                if (HAS_LO) {
                    uint32_t dstl = sBl + (uint32_t)(r * LDS_ROW + col * 8) * 2;
                    cp_async16(dstl, Blo + (size_t)rr * K + kk + col * 8, pred);
                }
            }
        }
        asm volatile("cp.async.commit_group;\n" ::);
    };

    auto compute_stage = [&](int s) {
        const uint32_t aB  = sbase + s * STAGE_BYTES;
        const uint32_t bhB = aB + STAGE_ONE_BYTES;
        const uint32_t blB = bhB + STAGE_ONE_BYTES;
#pragma unroll
        for (int k16 = 0; k16 < 2; k16++) {
            uint32_t afr[2][4];
#pragma unroll
            for (int mi = 0; mi < 2; mi++)
                ldm4(afr[mi], aB + (uint32_t)((wm * 32 + mi * 16 + roff) * LDS_ROW + k16 * 16 + koff) * 2);
#pragma unroll
            for (int nj = 0; nj < 4; nj++) {
                uint32_t boff = (uint32_t)((wn * 64 + nj * 16 + roff) * LDS_ROW + k16 * 16 + koff) * 2;
                uint32_t bfr[4];
                ldm4(bfr, bhB + boff);
                mma16816<F16>(acc[0][2 * nj + 0], afr[0], bfr[0], bfr[2]);
                mma16816<F16>(acc[1][2 * nj + 0], afr[1], bfr[0], bfr[2]);
                mma16816<F16>(acc[0][2 * nj + 1], afr[0], bfr[1], bfr[3]);
                mma16816<F16>(acc[1][2 * nj + 1], afr[1], bfr[1], bfr[3]);
                if (HAS_LO) {
                    uint32_t lfr[4];
                    ldm4(lfr, blB + boff);
                    mma16816<F16>(acc[0][2 * nj + 0], afr[0], lfr[0], lfr[2]);
                    mma16816<F16>(acc[1][2 * nj + 0], afr[1], lfr[0], lfr[2]);
                    mma16816<F16>(acc[0][2 * nj + 1], afr[0], lfr[1], lfr[3]);
                    mma16816<F16>(acc[1][2 * nj + 1], afr[1], lfr[1], lfr[3]);
                }
            }
        }
    };

#pragma unroll
    for (int s = 0; s < GSTAGES - 1; s++) issue_stage(s, s);

    for (int kt = 0; kt < KT; kt++) {
        asm volatile("cp.async.wait_group 1;\n" ::);
        __syncthreads();
        compute_stage(kt % GSTAGES);
        issue_stage(kt + GSTAGES - 1, (kt + GSTAGES - 1) % GSTAGES);
    }
    asm volatile("cp.async.wait_group 0;\n" ::);

    // Epilogue: BN (x * gamma/sqrt(1+eps) + beta), write fp32
    const float inv = rsqrtf(1.0f + 1e-5f);
    const int qr = lane >> 2;
    const int qc = (lane & 3) << 1;
#pragma unroll
    for (int ni = 0; ni < 8; ni++) {
        int n = n0 + wn * 64 + ni * 8 + qc;
        if (n >= N) continue;
        float g0 = gamma[n] * inv, b0 = beta[n];
        bool has2 = (n + 1 < N);
        float g1 = has2 ? gamma[n + 1] * inv : 0.0f;
        float b1 = has2 ? beta[n + 1] : 0.0f;
#pragma unroll
        for (int mi = 0; mi < 2; mi++) {
#pragma unroll
            for (int h = 0; h < 2; h++) {
                int row = m0 + wm * 32 + mi * 16 + qr + h * 8;
                float v0 = fmaf(acc[mi][ni][h * 2 + 0], g0, b0);
                float v1 = fmaf(acc[mi][ni][h * 2 + 1], g1, b1);
                float* cp = C + (size_t)row * N + n;
                if (has2) *reinterpret_cast<float2*>(cp) = make_float2(v0, v1);
                else      cp[0] = v0;
            }
        }
    }
}

#define SMEM_DUAL (GSTAGES * 3 * STAGE_ONE_BYTES)  // 92160
#define SMEM_SGL  (GSTAGES * 2 * STAGE_ONE_BYTES)  // 61440

// ---------------------------------------------------------------------------
// log-softmax over rows of [ROWS, OUTDIM], in place
// ---------------------------------------------------------------------------
__global__ void __launch_bounds__(256) logsoftmax_kernel(float* __restrict__ out) {
    __shared__ float sv[OUTDIM];
    __shared__ float red[9];
    const int tid = threadIdx.x, lane = tid & 31, warp = tid >> 5;
    float* p = out + (size_t)blockIdx.x * OUTDIM;

    float mx = -3.4e38f;
    for (int i = tid; i < OUTDIM; i += 256) { float v = p[i]; sv[i] = v; mx = fmaxf(mx, v); }
#pragma unroll
    for (int o = 16; o; o >>= 1) mx = fmaxf(mx, __shfl_xor_sync(0xffffffffu, mx, o));
    if (lane == 0) red[warp] = mx;
    __syncthreads();
    if (warp == 0) {
        float v = (lane < 8) ? red[lane] : -3.4e38f;
#pragma unroll
        for (int o = 4; o; o >>= 1) v = fmaxf(v, __shfl_xor_sync(0xffffffffu, v, o));
        if (lane == 0) red[8] = v;
    }
    __syncthreads();
    mx = red[8];

    float s = 0.0f;
    for (int i = tid; i < OUTDIM; i += 256) s += expf(sv[i] - mx);
#pragma unroll
    for (int o = 16; o; o >>= 1) s += __shfl_xor_sync(0xffffffffu, s, o);
    __syncthreads();
    if (lane == 0) red[warp] = s;
    __syncthreads();
    if (warp == 0) {
        float v = (lane < 8) ? red[lane] : 0.0f;
#pragma unroll
        for (int o = 4; o; o >>= 1) v += __shfl_xor_sync(0xffffffffu, v, o);
        if (lane == 0) red[8] = v;
    }
    __syncthreads();
    float lse = mx + logf(red[8]);
    for (int i = tid; i < OUTDIM; i += 256) p[i] = sv[i] - lse;
}

// ---------------------------------------------------------------------------
// Launch sequence
// ---------------------------------------------------------------------------
extern "C" void kernel_launch(void* const* d_in, const int* in_sizes, int n_in,
                              void* d_out, int out_size) {
    const float* xs   = (const float*)d_in[0];   // [500,64,440]
    const float* W0   = (const float*)d_in[1];   // [1024,440]
    const float* Ws   = (const float*)d_in[2];   // [3,1024,1024]
    const float* taus = (const float*)d_in[3];   // [4,1024]
    const float* bng  = (const float*)d_in[4];   // [4,1024]
    const float* bnb  = (const float*)d_in[5];   // [4,1024]
    const float* Wf   = (const float*)d_in[6];   // [1944,1024]
    const float* fg   = (const float*)d_in[7];   // [1944]
    const float* fb   = (const float*)d_in[8];   // [1944]
    float* out = (float*)d_out;

    void* p;
    cudaGetSymbolAddress(&p, g_actB); uint16_t* actB = (uint16_t*)p;
    cudaGetSymbolAddress(&p, g_actH); uint16_t* actH = (uint16_t*)p;
    cudaGetSymbolAddress(&p, g_ws);   float*    ws   = (float*)p;
    cudaGetSymbolAddress(&p, g_W0hi); uint16_t* w0hi = (uint16_t*)p;
    cudaGetSymbolAddress(&p, g_W0lo); uint16_t* w0lo = (uint16_t*)p;
    cudaGetSymbolAddress(&p, g_Wsh);  uint16_t* wsh  = (uint16_t*)p;
    cudaGetSymbolAddress(&p, g_Wfh);  uint16_t* wfh  = (uint16_t*)p;

    cudaFuncSetAttribute((const void*)gemm_bn_kernel<false, true>,
                         cudaFuncAttributeMaxDynamicSharedMemorySize, SMEM_DUAL);
    cudaFuncSetAttribute((const void*)gemm_bn_kernel<true, false>,
                         cudaFuncAttributeMaxDynamicSharedMemorySize, SMEM_SGL);

    // --- weight preparation (idempotent) ---
    split_weights_kernel<<<(HID * INPAD + 255) / 256, 256>>>(
        W0, (__nv_bfloat16*)w0hi, (__nv_bfloat16*)w0lo, HID, INDIM, INPAD);
    to_half_kernel<<<(3 * HID * HID + 255) / 256, 256>>>(
        Ws, (__half*)wsh, (long long)3 * HID * HID);
    to_half_kernel<<<((long long)OUTDIM * HID + 255) / 256, 256>>>(
        Wf, (__half*)wfh, (long long)OUTDIM * HID);

    // --- input FSQ scan -> actB [32000, 448] bf16 ---
    input_scan_kernel<<<(BATCH * INPAD + 127) / 128, 128>>>(xs, (__nv_bfloat16*)actB);

    dim3 gh(ROWS / BM, HID / BN);   // (250, 8)

    // layer 0 (bf16 hi+lo dual) -> spikes out in fp16 for layer 1
    gemm_bn_kernel<false, true><<<gh, 256, SMEM_DUAL>>>(
        actB, w0hi, w0lo, ws, HID, INPAD, bng, bnb);
    lif_scan_kernel<__half><<<(BATCH * HID) / 128, 128>>>(
        ws, taus, (__half*)actH);

    // layers 1..3 (fp16 single-pass)
    for (int l = 1; l < 4; l++) {
        gemm_bn_kernel<true, false><<<gh, 256, SMEM_SGL>>>(
            actH, wsh + (size_t)(l - 1) * HID * HID, nullptr,
            ws, HID, HID, bng + l * HID, bnb + l * HID);
        lif_scan_kernel<__half><<<(BATCH * HID) / 128, 128>>>(
            ws, taus + l * HID, (__half*)actH);
    }

    // final projection (fp16 single) -> d_out [32000, 1944] fp32
    dim3 gf(ROWS / BM, (OUTDIM + BN - 1) / BN);  // (250, 16)
    gemm_bn_kernel<true, false><<<gf, 256, SMEM_SGL>>>(
        actH, wfh, nullptr, out, OUTDIM, HID, fg, fb);

    // in-place log-softmax per row
    logsoftmax_kernel<<<ROWS, 256>>>(out);
}